// round 7
// baseline (speedup 1.0000x reference)
#include <cuda_runtime.h>
#include <math.h>

#define NB 8
#define NT 16384
#define NQ 256
#define NR 64
#define ND 64
#define NS 256
#define NL 20
#define OUTW 14337
#define OUTW_PAD 14368
#define TT 256
#define AS 258   // padded act row stride

typedef unsigned long long ull;

__device__ __forceinline__ ull pack2(float x) {
    ull r; asm("mov.b64 %0, {%1, %1};" : "=l"(r) : "f"(x)); return r;
}
__device__ __forceinline__ ull pack2(float lo, float hi) {
    ull r; asm("mov.b64 %0, {%1, %2};" : "=l"(r) : "f"(lo), "f"(hi)); return r;
}
__device__ __forceinline__ void fma2(ull& d, ull a, ull b) {
    asm("fma.rn.f32x2 %0, %1, %2, %0;" : "+l"(d) : "l"(a), "l"(b));
}
__device__ __forceinline__ float2 u2f(ull v) {
    float2 f; asm("mov.b64 {%0, %1}, %2;" : "=f"(f.x), "=f"(f.y) : "l"(v)); return f;
}

// Scratch (device globals; no allocation allowed)
__device__ float g_h0[NB * NR * NT];
__device__ float g_h1[NB * NR * NT];
__device__ float g_acts[NL * NB * NR * OUTW_PAD];   // gated activations per layer (skip inputs)
__device__ float g_swT[NL * ND * NS];               // [k=li*64+dc][s]
__device__ float g_sbsum[NS];
__device__ float g_w1T[NS * NS];
__device__ float g_w2T[NQ * NS];

// wT[k][s] = w[s][k], 256x256
__global__ void transpose_kernel(const float* __restrict__ w, float* __restrict__ wT) {
    int i = blockIdx.x * 256 + threadIdx.x;
    int k = i >> 8, s = i & 255;
    wT[i] = w[(s << 8) + k];
}

// swT[k][s] = skip_w[li][s][dc], k = li*64+dc
__global__ void skipw_kernel(const float* __restrict__ sw, float* __restrict__ swT) {
    int k = blockIdx.x;          // 0..1279
    int s = threadIdx.x;         // 0..255
    int li = k >> 6, dc = k & 63;
    swT[k * NS + s] = sw[li * (NS * ND) + s * ND + dc];
}

// sbsum[s] = sum_li skip_b[li][s]
__global__ void sbsum_kernel(const float* __restrict__ sb, float* __restrict__ sbsum) {
    int s = threadIdx.x;
    float v = 0.f;
    #pragma unroll
    for (int li = 0; li < NL; li++) v += sb[li * NS + s];
    sbsum[s] = v;
}

// h[b][r][t] = cw[r][x[b,t]][0] + cw[r][x[b,t+1]][1] + cb[r]   (one-hot conv == gather)
__global__ void __launch_bounds__(256) causal_kernel(
    const int* __restrict__ x, const float* __restrict__ cw,
    const float* __restrict__ cb, float* __restrict__ h)
{
    extern __shared__ float sm[];               // 32768 floats: cw [r][q][k]
    __shared__ float cbS[64];
    for (int i = threadIdx.x; i < NR * NQ * 2; i += 256) sm[i] = cw[i];
    if (threadIdx.x < 64) cbS[threadIdx.x] = cb[threadIdx.x];
    __syncthreads();
    int b = blockIdx.y;
    int t = blockIdx.x * 256 + threadIdx.x;
    if (t >= NT - 1) return;
    int q0 = x[b * NT + t] * 2;
    int q1 = x[b * NT + t + 1] * 2 + 1;
    float* hp = h + ((size_t)b << 20) + t;
    #pragma unroll 4
    for (int r = 0; r < 64; r++) {
        hp[r << 14] = sm[(r << 9) + q0] + sm[(r << 9) + q1] + cbS[r];
    }
}

// Fused WaveNet layer (no skip), 1024 threads, 256 time cols per CTA.
// Phase 1 mapping: lane = channel-pair (broadcast act loads), warp = 8 time cols.
// SMEM layout (floats):
//   [0, 8192)        wfT (k,r,dc)       -- dead after phase1
//   [8192, 16384)    wgT (k,r,dc)       -- dead after phase1
//   [0, 16512)       act [64][258]      -- written after phase1 (overlaps wfT/wgT)
//   [16512, 20608)   dwS [r][dc]
//   [20608, 36992)   hA  [64][256]      -- dead after phase1
//   [36992, 53376)   hB  [64][256]
// total 53376 floats = 213504 B
__global__ void __launch_bounds__(1024) layer_kernel(
    const float* __restrict__ hcur, float* __restrict__ hnext,
    const float* __restrict__ fw, const float* __restrict__ fb,
    const float* __restrict__ gw, const float* __restrict__ gb,
    const float* __restrict__ dw, const float* __restrict__ db,
    float* __restrict__ acts,
    int li, int dil, int Lh, int Ti, int off)
{
    extern __shared__ float smem[];
    float* wfT = smem;
    float* wgT = smem + 8192;
    float* act = smem;              // [64][258], valid after phase1
    float* dwS = smem + 16512;
    float* hA  = smem + 20608;
    float* hB  = smem + 36992;

    const int tid = threadIdx.x;
    const int b = blockIdx.y;
    const int t0 = blockIdx.x * TT;

    // stage weights; fw/gw transposed to (k,r,dc) so inner reads are conflict-free
    #pragma unroll 1
    for (int i = tid; i < 8192; i += 1024) {
        int dcq = i >> 7, r = (i >> 1) & 63, k = i & 1;
        int si = (k << 12) + (r << 6) + dcq;
        wfT[si] = fw[i];
        wgT[si] = gw[i];
    }
    for (int i = tid; i < 4096; i += 1024) dwS[i] = dw[i];

    const float* hbase = hcur + ((size_t)b << 20);
    #pragma unroll 1
    for (int i = tid; i < 64 * TT; i += 1024) {
        int r = i >> 8, tt = i & 255;
        int ta = t0 + tt;
        hA[i] = (ta < Lh) ? hbase[(r << 14) + ta] : 0.f;
        int tb = ta + dil;
        hB[i] = (tb < Lh) ? hbase[(r << 14) + tb] : 0.f;
    }
    __syncthreads();

    // ---- Phase 1: filter/gate GEMM (K=64, 2 taps) ----
    // lane -> channel pair (2*lane, 2*lane+1), warp -> times tg*8 .. tg*8+7
    const int lane = tid & 31;
    const int tg = tid >> 5;        // 0..31
    const int dc0 = lane << 1;
    ull fa[2][4], ga[2][4];         // [channel][time-pair]
    {
        ull fb0 = pack2(fb[dc0]), fb1 = pack2(fb[dc0 + 1]);
        ull gb0 = pack2(gb[dc0]), gb1 = pack2(gb[dc0 + 1]);
        #pragma unroll
        for (int p = 0; p < 4; p++) {
            fa[0][p] = fb0; fa[1][p] = fb1;
            ga[0][p] = gb0; ga[1][p] = gb1;
        }
        const float* hap = hA + (tg << 3);
        const float* hbp = hB + (tg << 3);
        #pragma unroll 2
        for (int r = 0; r < 64; r++) {
            // act loads: identical address across warp -> broadcast wavefronts
            ulonglong2 A0 = *(const ulonglong2*)(hap + (r << 8));
            ulonglong2 A1 = *(const ulonglong2*)(hap + (r << 8) + 4);
            ulonglong2 C0 = *(const ulonglong2*)(hbp + (r << 8));
            ulonglong2 C1 = *(const ulonglong2*)(hbp + (r << 8) + 4);
            // weights: LDS.64 per channel pair, conflict-free
            float2 wf0 = *(const float2*)(wfT + (r << 6) + dc0);
            float2 wf1 = *(const float2*)(wfT + 4096 + (r << 6) + dc0);
            float2 wg0 = *(const float2*)(wgT + (r << 6) + dc0);
            float2 wg1 = *(const float2*)(wgT + 4096 + (r << 6) + dc0);
            {
                ull w0 = pack2(wf0.x), w1 = pack2(wf0.y);
                fma2(fa[0][0], w0, A0.x); fma2(fa[0][1], w0, A0.y);
                fma2(fa[0][2], w0, A1.x); fma2(fa[0][3], w0, A1.y);
                fma2(fa[1][0], w1, A0.x); fma2(fa[1][1], w1, A0.y);
                fma2(fa[1][2], w1, A1.x); fma2(fa[1][3], w1, A1.y);
            }
            {
                ull w0 = pack2(wf1.x), w1 = pack2(wf1.y);
                fma2(fa[0][0], w0, C0.x); fma2(fa[0][1], w0, C0.y);
                fma2(fa[0][2], w0, C1.x); fma2(fa[0][3], w0, C1.y);
                fma2(fa[1][0], w1, C0.x); fma2(fa[1][1], w1, C0.y);
                fma2(fa[1][2], w1, C1.x); fma2(fa[1][3], w1, C1.y);
            }
            {
                ull w0 = pack2(wg0.x), w1 = pack2(wg0.y);
                fma2(ga[0][0], w0, A0.x); fma2(ga[0][1], w0, A0.y);
                fma2(ga[0][2], w0, A1.x); fma2(ga[0][3], w0, A1.y);
                fma2(ga[1][0], w1, A0.x); fma2(ga[1][1], w1, A0.y);
                fma2(ga[1][2], w1, A1.x); fma2(ga[1][3], w1, A1.y);
            }
            {
                ull w0 = pack2(wg1.x), w1 = pack2(wg1.y);
                fma2(ga[0][0], w0, C0.x); fma2(ga[0][1], w0, C0.y);
                fma2(ga[0][2], w0, C1.x); fma2(ga[0][3], w0, C1.y);
                fma2(ga[1][0], w1, C0.x); fma2(ga[1][1], w1, C0.y);
                fma2(ga[1][2], w1, C1.x); fma2(ga[1][3], w1, C1.y);
            }
        }
        // out = tanh(f) * sigmoid(g)
        #pragma unroll
        for (int c = 0; c < 2; c++) {
            #pragma unroll
            for (int p = 0; p < 4; p++) {
                float2 f = u2f(fa[c][p]);
                float2 g = u2f(ga[c][p]);
                float ef0 = __expf(fminf(-2.f * f.x, 80.f));
                float ef1 = __expf(fminf(-2.f * f.y, 80.f));
                float eg0 = __expf(fminf(-g.x, 80.f));
                float eg1 = __expf(fminf(-g.y, 80.f));
                float o0 = __fdividef(1.f - ef0, (1.f + ef0) * (1.f + eg0));
                float o1 = __fdividef(1.f - ef1, (1.f + ef1) * (1.f + eg1));
                fa[c][p] = pack2(o0, o1);
            }
        }
    }
    __syncthreads();    // all wfT/wgT/hA reads done

    // write activation tile (rows dc0, dc0+1; cols tg*8..tg*8+7)
    {
        #pragma unroll
        for (int c = 0; c < 2; c++) {
            float* row = act + (dc0 + c) * AS + (tg << 3);
            #pragma unroll
            for (int p = 0; p < 4; p++)
                *(float2*)(row + (p << 1)) = u2f(fa[c][p]);
        }
    }
    __syncthreads();

    // store act tile to global (skip input), cols >= off, aligned to skip index
    {
        float* abase = acts + (size_t)((li * NB + b) * 64) * OUTW_PAD - off;
        #pragma unroll 1
        for (int i = tid; i < 64 * TT; i += 1024) {
            int dcw = i >> 8, tt = i & 255;
            int tgl = t0 + tt;
            if (tgl >= off && tgl < Ti)
                abase[(size_t)dcw * OUTW_PAD + tgl] = act[dcw * AS + tt];
        }
    }

    const int tl = tid & 31;
    const int wp = tid >> 5;   // 0..31 -> r pair (2wp, 2wp+1)

    // ---- Phase 2: dense 1x1 (D->R) + residual -> hnext ----
    {
        const int r0 = wp << 1;
        ull acc[2][4];
        acc[0][0] = acc[0][1] = acc[0][2] = acc[0][3] = pack2(db[r0]);
        acc[1][0] = acc[1][1] = acc[1][2] = acc[1][3] = pack2(db[r0 + 1]);
        #pragma unroll 1
        for (int dcc = 0; dcc < 64; dcc++) {
            const float* ar = act + dcc * AS + (tl << 1);
            ull o[4];
            #pragma unroll
            for (int p = 0; p < 4; p++) o[p] = *(const ull*)(ar + (p << 6));
            ull w0 = pack2(dwS[(r0 << 6) + dcc]);          // broadcast
            ull w1 = pack2(dwS[((r0 + 1) << 6) + dcc]);    // broadcast
            #pragma unroll
            for (int p = 0; p < 4; p++) {
                fma2(acc[0][p], w0, o[p]);
                fma2(acc[1][p], w1, o[p]);
            }
        }
        float* hnb = hnext + ((size_t)b << 20);
        #pragma unroll
        for (int m = 0; m < 2; m++) {
            int r = r0 + m;
            #pragma unroll
            for (int p = 0; p < 4; p++) {
                int tt = (tl << 1) + (p << 6);
                int tgl = t0 + tt;
                float2 hv = *(const float2*)(hB + (r << 8) + tt);
                float2 v = u2f(acc[m][p]);
                v.x += hv.x; v.y += hv.y;
                if (tgl + 1 < Ti) {
                    *(float2*)(hnb + (r << 14) + tgl) = v;
                } else if (tgl < Ti) {
                    hnb[(r << 14) + tgl] = v.x;
                }
            }
        }
    }
}

// Fused post chain: total(K=1280 GEMM over acts) -> +sbsum,relu -> pp1(K=256)
//   -> +b1,relu -> pp2(K=256) -> +b2 -> out.   1024 threads, 128 time cols/CTA.
// smem: inS [64][128]=8192, wS [64][256]=16384, buf [256][128]=32768 -> 57344 floats
__global__ void __launch_bounds__(1024) fused_post_kernel(
    const float* __restrict__ acts, const float* __restrict__ swT,
    const float* __restrict__ sbsum,
    const float* __restrict__ w1T, const float* __restrict__ b1,
    const float* __restrict__ w2T, const float* __restrict__ b2,
    float* __restrict__ outp)
{
    extern __shared__ float smem[];
    float* inS = smem;            // [64][128]
    float* wS  = smem + 8192;     // [64][256]
    float* buf = smem + 24576;    // [256][128]
    const int tid = threadIdx.x;
    const int b = blockIdx.y;
    const int t0 = blockIdx.x << 7;
    const int tl = tid & 31;
    const int wp = tid >> 5;      // 0..31

    // ---- Stage A: skip GEMM, K = 20 layers x 64 channels ----
    ull acc[4][4];
    #pragma unroll
    for (int mp = 0; mp < 4; mp++)
        #pragma unroll
        for (int q = 0; q < 4; q++) acc[mp][q] = 0ULL;

    #pragma unroll 1
    for (int li = 0; li < NL; li++) {
        __syncthreads();
        const float* ab = acts + (size_t)((li * NB + b) * 64) * OUTW_PAD;
        #pragma unroll 1
        for (int i = tid; i < 8192; i += 1024) {
            int dcr = i >> 7, tt = i & 127;
            int t = t0 + tt;
            inS[i] = (t < OUTW) ? ab[(size_t)dcr * OUTW_PAD + t] : 0.f;
        }
        #pragma unroll 1
        for (int i = tid; i < 16384; i += 1024) wS[i] = swT[li * 16384 + i];
        __syncthreads();
        #pragma unroll 1
        for (int kk = 0; kk < 64; kk++) {
            const float* ir = inS + (kk << 7) + tl;
            ull o[4];
            #pragma unroll
            for (int q = 0; q < 4; q++) o[q] = pack2(ir[q << 5]);
            const float* wr = wS + (kk << 8) + (wp << 1);
            #pragma unroll
            for (int mp = 0; mp < 4; mp++) {
                ull w = *(const ull*)(wr + (mp << 6));
                #pragma unroll
                for (int q = 0; q < 4; q++) fma2(acc[mp][q], w, o[q]);
            }
        }
    }
    // total + biasSum, relu -> buf
    #pragma unroll
    for (int mp = 0; mp < 4; mp++) {
        int s0 = (wp << 1) + (mp << 6);
        float sb0 = sbsum[s0], sb1 = sbsum[s0 + 1];
        #pragma unroll
        for (int q = 0; q < 4; q++) {
            float2 v = u2f(acc[mp][q]);
            int tt = tl + (q << 5);
            buf[(s0 << 7) + tt]       = fmaxf(v.x + sb0, 0.f);
            buf[((s0 + 1) << 7) + tt] = fmaxf(v.y + sb1, 0.f);
        }
    }

    // ---- Stage B: pp1 (K=256) ----
    #pragma unroll
    for (int mp = 0; mp < 4; mp++) {
        int s0 = (wp << 1) + (mp << 6);
        ull bv = pack2(b1[s0], b1[s0 + 1]);
        #pragma unroll
        for (int q = 0; q < 4; q++) acc[mp][q] = bv;
    }
    #pragma unroll 1
    for (int kc = 0; kc < 4; kc++) {
        __syncthreads();
        #pragma unroll 1
        for (int i = tid; i < 16384; i += 1024) wS[i] = w1T[(kc << 14) + i];
        __syncthreads();
        #pragma unroll 1
        for (int kk = 0; kk < 64; kk++) {
            const float* ir = buf + (((kc << 6) + kk) << 7) + tl;
            ull o[4];
            #pragma unroll
            for (int q = 0; q < 4; q++) o[q] = pack2(ir[q << 5]);
            const float* wr = wS + (kk << 8) + (wp << 1);
            #pragma unroll
            for (int mp = 0; mp < 4; mp++) {
                ull w = *(const ull*)(wr + (mp << 6));
                #pragma unroll
                for (int q = 0; q < 4; q++) fma2(acc[mp][q], w, o[q]);
            }
        }
    }
    __syncthreads();   // all pp1 reads of buf done
    #pragma unroll
    for (int mp = 0; mp < 4; mp++) {
        int s0 = (wp << 1) + (mp << 6);
        #pragma unroll
        for (int q = 0; q < 4; q++) {
            float2 v = u2f(acc[mp][q]);
            int tt = tl + (q << 5);
            buf[(s0 << 7) + tt]       = fmaxf(v.x, 0.f);
            buf[((s0 + 1) << 7) + tt] = fmaxf(v.y, 0.f);
        }
    }

    // ---- Stage C: pp2 (K=256) -> global out ----
    #pragma unroll
    for (int mp = 0; mp < 4; mp++) {
        int s0 = (wp << 1) + (mp << 6);
        ull bv = pack2(b2[s0], b2[s0 + 1]);
        #pragma unroll
        for (int q = 0; q < 4; q++) acc[mp][q] = bv;
    }
    #pragma unroll 1
    for (int kc = 0; kc < 4; kc++) {
        __syncthreads();
        #pragma unroll 1
        for (int i = tid; i < 16384; i += 1024) wS[i] = w2T[(kc << 14) + i];
        __syncthreads();
        #pragma unroll 1
        for (int kk = 0; kk < 64; kk++) {
            const float* ir = buf + (((kc << 6) + kk) << 7) + tl;
            ull o[4];
            #pragma unroll
            for (int q = 0; q < 4; q++) o[q] = pack2(ir[q << 5]);
            const float* wr = wS + (kk << 8) + (wp << 1);
            #pragma unroll
            for (int mp = 0; mp < 4; mp++) {
                ull w = *(const ull*)(wr + (mp << 6));
                #pragma unroll
                for (int q = 0; q < 4; q++) fma2(acc[mp][q], w, o[q]);
            }
        }
    }
    #pragma unroll
    for (int mp = 0; mp < 4; mp++) {
        int s0 = (wp << 1) + (mp << 6);
        float* op0 = outp + (size_t)((b << 8) + s0) * OUTW + t0;
        float* op1 = op0 + OUTW;
        #pragma unroll
        for (int q = 0; q < 4; q++) {
            int tt = tl + (q << 5);
            if (t0 + tt < OUTW) {
                float2 v = u2f(acc[mp][q]);
                op0[tt] = v.x;
                op1[tt] = v.y;
            }
        }
    }
}

extern "C" void kernel_launch(void* const* d_in, const int* in_sizes, int n_in,
                              void* d_out, int out_size)
{
    const int*   x        = (const int*)d_in[0];
    const float* causal_w = (const float*)d_in[1];
    const float* causal_b = (const float*)d_in[2];
    const float* filt_w   = (const float*)d_in[3];
    const float* filt_b   = (const float*)d_in[4];
    const float* gate_w   = (const float*)d_in[5];
    const float* gate_b   = (const float*)d_in[6];
    const float* dense_w  = (const float*)d_in[7];
    const float* dense_b  = (const float*)d_in[8];
    const float* skip_w   = (const float*)d_in[9];
    const float* skip_b   = (const float*)d_in[10];
    const float* pp1_w    = (const float*)d_in[11];
    const float* pp1_b    = (const float*)d_in[12];
    const float* pp2_w    = (const float*)d_in[13];
    const float* pp2_b    = (const float*)d_in[14];
    float* out = (float*)d_out;

    float *h0, *h1, *acts, *swT, *sbsum, *w1T, *w2T;
    cudaGetSymbolAddress((void**)&h0, g_h0);
    cudaGetSymbolAddress((void**)&h1, g_h1);
    cudaGetSymbolAddress((void**)&acts, g_acts);
    cudaGetSymbolAddress((void**)&swT, g_swT);
    cudaGetSymbolAddress((void**)&sbsum, g_sbsum);
    cudaGetSymbolAddress((void**)&w1T, g_w1T);
    cudaGetSymbolAddress((void**)&w2T, g_w2T);

    static const int dil[NL] = {1, 2, 4, 8, 16, 32, 64, 128, 256, 512,
                                1, 2, 4, 8, 16, 32, 64, 128, 256, 512};

    cudaFuncSetAttribute(layer_kernel,      cudaFuncAttributeMaxDynamicSharedMemorySize, 53376 * 4);
    cudaFuncSetAttribute(causal_kernel,     cudaFuncAttributeMaxDynamicSharedMemorySize, 32768 * 4);
    cudaFuncSetAttribute(fused_post_kernel, cudaFuncAttributeMaxDynamicSharedMemorySize, 57344 * 4);

    // prep (independent of layer chain)
    transpose_kernel<<<256, 256>>>(pp1_w, w1T);
    transpose_kernel<<<256, 256>>>(pp2_w, w2T);
    skipw_kernel<<<NL * ND, 256>>>(skip_w, swT);
    sbsum_kernel<<<1, 256>>>(skip_b, sbsum);

    dim3 cg((NT - 1 + 255) / 256, NB);
    causal_kernel<<<cg, 256, 32768 * 4>>>(x, causal_w, causal_b, h0);

    float* hc = h0;
    float* hn = h1;
    int Lh = NT - 1;
    for (int i = 0; i < NL; i++) {
        int d = dil[i];
        int Ti = Lh - d;
        int off = Ti - OUTW;
        dim3 g((Ti + TT - 1) / TT, NB);
        layer_kernel<<<g, 1024, 53376 * 4>>>(
            hc, hn,
            filt_w + (size_t)i * ND * NR * 2, filt_b + (size_t)i * ND,
            gate_w + (size_t)i * ND * NR * 2, gate_b + (size_t)i * ND,
            dense_w + (size_t)i * NR * ND,    dense_b + (size_t)i * NR,
            acts, i, d, Lh, Ti, off);
        float* tmp = hc; hc = hn; hn = tmp;
        Lh = Ti;
    }

    dim3 pg((OUTW + 127) / 128, NB);
    fused_post_kernel<<<pg, 1024, 57344 * 4>>>(acts, swT, sbsum,
                                               w1T, pp1_b, w2T, pp2_b, out);
}

// round 8
// speedup vs baseline: 1.5633x; 1.5633x over previous
#include <cuda_runtime.h>
#include <math.h>

#define NB 8
#define NT 16384
#define NQ 256
#define NR 64
#define ND 64
#define NS 256
#define NL 20
#define OUTW 14337
#define OUTW_PAD 14368
#define TT 256
#define AS 258   // padded act row stride

typedef unsigned long long ull;

__device__ __forceinline__ ull pack2(float x) {
    ull r; asm("mov.b64 %0, {%1, %1};" : "=l"(r) : "f"(x)); return r;
}
__device__ __forceinline__ ull pack2(float lo, float hi) {
    ull r; asm("mov.b64 %0, {%1, %2};" : "=l"(r) : "f"(lo), "f"(hi)); return r;
}
__device__ __forceinline__ void fma2(ull& d, ull a, ull b) {
    asm("fma.rn.f32x2 %0, %1, %2, %0;" : "+l"(d) : "l"(a), "l"(b));
}
__device__ __forceinline__ float2 u2f(ull v) {
    float2 f; asm("mov.b64 {%0, %1}, %2;" : "=f"(f.x), "=f"(f.y) : "l"(v)); return f;
}

// Scratch (device globals; no allocation allowed)
__device__ float g_h0[NB * NR * NT];
__device__ float g_h1[NB * NR * NT];
__device__ float g_acts[NL * NB * NR * OUTW_PAD];   // gated activations per layer (skip inputs)
__device__ float g_swT[NL * ND * NS];               // [k=li*64+dc][s]
__device__ float g_sbsum[NS];
__device__ float g_w1T[NS * NS];
__device__ float g_w2T[NQ * NS];

// wT[k][s] = w[s][k], 256x256
__global__ void transpose_kernel(const float* __restrict__ w, float* __restrict__ wT) {
    int i = blockIdx.x * 256 + threadIdx.x;
    int k = i >> 8, s = i & 255;
    wT[i] = w[(s << 8) + k];
}

// swT[k][s] = skip_w[li][s][dc], k = li*64+dc
__global__ void skipw_kernel(const float* __restrict__ sw, float* __restrict__ swT) {
    int k = blockIdx.x;          // 0..1279
    int s = threadIdx.x;         // 0..255
    int li = k >> 6, dc = k & 63;
    swT[k * NS + s] = sw[li * (NS * ND) + s * ND + dc];
}

// sbsum[s] = sum_li skip_b[li][s]
__global__ void sbsum_kernel(const float* __restrict__ sb, float* __restrict__ sbsum) {
    int s = threadIdx.x;
    float v = 0.f;
    #pragma unroll
    for (int li = 0; li < NL; li++) v += sb[li * NS + s];
    sbsum[s] = v;
}

// h[b][r][t] = cw[r][x[b,t]][0] + cw[r][x[b,t+1]][1] + cb[r]   (one-hot conv == gather)
__global__ void __launch_bounds__(256) causal_kernel(
    const int* __restrict__ x, const float* __restrict__ cw,
    const float* __restrict__ cb, float* __restrict__ h)
{
    extern __shared__ float sm[];               // 32768 floats: cw [r][q][k]
    __shared__ float cbS[64];
    for (int i = threadIdx.x; i < NR * NQ * 2; i += 256) sm[i] = cw[i];
    if (threadIdx.x < 64) cbS[threadIdx.x] = cb[threadIdx.x];
    __syncthreads();
    int b = blockIdx.y;
    int t = blockIdx.x * 256 + threadIdx.x;
    if (t >= NT - 1) return;
    int q0 = x[b * NT + t] * 2;
    int q1 = x[b * NT + t + 1] * 2 + 1;
    float* hp = h + ((size_t)b << 20) + t;
    #pragma unroll 4
    for (int r = 0; r < 64; r++) {
        hp[r << 14] = sm[(r << 9) + q0] + sm[(r << 9) + q1] + cbS[r];
    }
}

// Fused WaveNet layer (no skip), 1024 threads, 256 time cols per CTA.
// Phase 1: thread tile = 4 channels x 4 time cols; weights channel-packed (ull),
// h splat into both lanes. Per warp per r: 12 smem wavefronts vs 32 FFMA2.
// SMEM layout (floats):
//   [0, 8192)        wfT (k,r,dc)       -- dead after phase1
//   [8192, 16384)    wgT (k,r,dc)       -- dead after phase1
//   [0, 16512)       act [64][258]      -- written after phase1 (overlaps wfT/wgT)
//   [16512, 20608)   dwS [r][dc]
//   [20608, 36992)   hA  [64][256]      -- dead after phase1
//   [36992, 53376)   hB  [64][256]
// total 53376 floats = 213504 B
__global__ void __launch_bounds__(1024) layer_kernel(
    const float* __restrict__ hcur, float* __restrict__ hnext,
    const float* __restrict__ fw, const float* __restrict__ fb,
    const float* __restrict__ gw, const float* __restrict__ gb,
    const float* __restrict__ dw, const float* __restrict__ db,
    float* __restrict__ acts,
    int li, int dil, int Lh, int Ti, int off)
{
    extern __shared__ float smem[];
    float* wfT = smem;
    float* wgT = smem + 8192;
    float* act = smem;              // [64][258], valid after phase1
    float* dwS = smem + 16512;
    float* hA  = smem + 20608;
    float* hB  = smem + 36992;

    const int tid = threadIdx.x;
    const int b = blockIdx.y;
    const int t0 = blockIdx.x * TT;

    // stage weights; fw/gw transposed to (k,r,dc) so inner reads are conflict-free
    #pragma unroll 1
    for (int i = tid; i < 8192; i += 1024) {
        int dcq = i >> 7, r = (i >> 1) & 63, k = i & 1;
        int si = (k << 12) + (r << 6) + dcq;
        wfT[si] = fw[i];
        wgT[si] = gw[i];
    }
    for (int i = tid; i < 4096; i += 1024) dwS[i] = dw[i];

    const float* hbase = hcur + ((size_t)b << 20);
    #pragma unroll 1
    for (int i = tid; i < 64 * TT; i += 1024) {
        int r = i >> 8, tt = i & 255;
        int ta = t0 + tt;
        hA[i] = (ta < Lh) ? hbase[(r << 14) + ta] : 0.f;
        int tb = ta + dil;
        hB[i] = (tb < Lh) ? hbase[(r << 14) + tb] : 0.f;
    }
    __syncthreads();

    // ---- Phase 1: filter/gate GEMM (K=64, 2 taps) ----
    // cg = col group (4 cols), dg = channel group (4 channels)
    const int cg = tid & 63;
    const int dg = tid >> 6;         // 0..15
    const int dc0 = dg << 2;
    ull facc[2][4], gacc[2][4];      // [channel pair][col], channel-packed
    {
        ull fbp0 = pack2(fb[dc0], fb[dc0 + 1]);
        ull fbp1 = pack2(fb[dc0 + 2], fb[dc0 + 3]);
        ull gbp0 = pack2(gb[dc0], gb[dc0 + 1]);
        ull gbp1 = pack2(gb[dc0 + 2], gb[dc0 + 3]);
        #pragma unroll
        for (int c = 0; c < 4; c++) {
            facc[0][c] = fbp0; facc[1][c] = fbp1;
            gacc[0][c] = gbp0; gacc[1][c] = gbp1;
        }
        const float* hap = hA + (cg << 2);
        const float* hbp = hB + (cg << 2);
        #pragma unroll 2
        for (int r = 0; r < 64; r++) {
            float4 A = *(const float4*)(hap + (r << 8));
            float4 C = *(const float4*)(hbp + (r << 8));
            ull a[4], c2[4];
            a[0] = pack2(A.x); a[1] = pack2(A.y); a[2] = pack2(A.z); a[3] = pack2(A.w);
            c2[0] = pack2(C.x); c2[1] = pack2(C.y); c2[2] = pack2(C.z); c2[3] = pack2(C.w);
            // filter weights (broadcast LDS.128: channel pairs)
            {
                ulonglong2 W0 = *(const ulonglong2*)(wfT + (r << 6) + dc0);
                ulonglong2 W1 = *(const ulonglong2*)(wfT + 4096 + (r << 6) + dc0);
                #pragma unroll
                for (int c = 0; c < 4; c++) {
                    fma2(facc[0][c], W0.x, a[c]);
                    fma2(facc[1][c], W0.y, a[c]);
                    fma2(facc[0][c], W1.x, c2[c]);
                    fma2(facc[1][c], W1.y, c2[c]);
                }
            }
            // gate weights
            {
                ulonglong2 W0 = *(const ulonglong2*)(wgT + (r << 6) + dc0);
                ulonglong2 W1 = *(const ulonglong2*)(wgT + 4096 + (r << 6) + dc0);
                #pragma unroll
                for (int c = 0; c < 4; c++) {
                    fma2(gacc[0][c], W0.x, a[c]);
                    fma2(gacc[1][c], W0.y, a[c]);
                    fma2(gacc[0][c], W1.x, c2[c]);
                    fma2(gacc[1][c], W1.y, c2[c]);
                }
            }
        }
        // out = tanh(f) * sigmoid(g)  (elementwise; lanes are channels here)
        #pragma unroll
        for (int p = 0; p < 2; p++) {
            #pragma unroll
            for (int c = 0; c < 4; c++) {
                float2 f = u2f(facc[p][c]);
                float2 g = u2f(gacc[p][c]);
                float ef0 = __expf(fminf(-2.f * f.x, 80.f));
                float ef1 = __expf(fminf(-2.f * f.y, 80.f));
                float eg0 = __expf(fminf(-g.x, 80.f));
                float eg1 = __expf(fminf(-g.y, 80.f));
                float o0 = __fdividef(1.f - ef0, (1.f + ef0) * (1.f + eg0));
                float o1 = __fdividef(1.f - ef1, (1.f + ef1) * (1.f + eg1));
                facc[p][c] = pack2(o0, o1);
            }
        }
    }
    __syncthreads();    // all wfT/wgT/hA reads done

    // write activation tile: rows dc0..dc0+3, cols 4cg..4cg+3
    {
        #pragma unroll
        for (int p = 0; p < 2; p++) {
            float* row0 = act + (dc0 + (p << 1)) * AS + (cg << 2);
            float* row1 = row0 + AS;
            #pragma unroll
            for (int c = 0; c < 4; c++) {
                float2 v = u2f(facc[p][c]);
                row0[c] = v.x;
                row1[c] = v.y;
            }
        }
    }
    __syncthreads();

    // store act tile to global (skip input), cols >= off, aligned to skip index
    {
        float* abase = acts + (size_t)((li * NB + b) * 64) * OUTW_PAD - off;
        #pragma unroll 1
        for (int i = tid; i < 64 * TT; i += 1024) {
            int dcw = i >> 8, tt = i & 255;
            int tgl = t0 + tt;
            if (tgl >= off && tgl < Ti)
                abase[(size_t)dcw * OUTW_PAD + tgl] = act[dcw * AS + tt];
        }
    }

    const int tl = tid & 31;
    const int wp = tid >> 5;   // 0..31

    // ---- Phase 2: dense 1x1 (D->R) + residual -> hnext, time-packed ----
    {
        ull acc[2][4];
        acc[0][0] = acc[0][1] = acc[0][2] = acc[0][3] = pack2(db[wp]);
        acc[1][0] = acc[1][1] = acc[1][2] = acc[1][3] = pack2(db[wp + 32]);
        #pragma unroll 1
        for (int dcc = 0; dcc < 64; dcc++) {
            const float* ar = act + dcc * AS + (tl << 1);
            ull o[4];
            #pragma unroll
            for (int p = 0; p < 4; p++) o[p] = *(const ull*)(ar + (p << 6));
            ull w0 = pack2(dwS[(wp << 6) + dcc]);           // broadcast
            ull w1 = pack2(dwS[((wp + 32) << 6) + dcc]);    // broadcast
            #pragma unroll
            for (int p = 0; p < 4; p++) {
                fma2(acc[0][p], w0, o[p]);
                fma2(acc[1][p], w1, o[p]);
            }
        }
        float* hnb = hnext + ((size_t)b << 20);
        #pragma unroll
        for (int m = 0; m < 2; m++) {
            int r = wp + (m << 5);
            #pragma unroll
            for (int p = 0; p < 4; p++) {
                int tt = (tl << 1) + (p << 6);
                int tgl = t0 + tt;
                float2 hv = *(const float2*)(hB + (r << 8) + tt);
                float2 v = u2f(acc[m][p]);
                v.x += hv.x; v.y += hv.y;
                if (tgl + 1 < Ti) {
                    *(float2*)(hnb + (r << 14) + tgl) = v;
                } else if (tgl < Ti) {
                    hnb[(r << 14) + tgl] = v.x;
                }
            }
        }
    }
}

// Fused post chain: total(K=1280 GEMM over acts) -> +sbsum,relu -> pp1(K=256)
//   -> +b1,relu -> pp2(K=256) -> +b2 -> out.   1024 threads, 128 time cols/CTA.
// smem: inS [64][128]=8192, wS [64][256]=16384, buf [256][128]=32768 -> 57344 floats
__global__ void __launch_bounds__(1024) fused_post_kernel(
    const float* __restrict__ acts, const float* __restrict__ swT,
    const float* __restrict__ sbsum,
    const float* __restrict__ w1T, const float* __restrict__ b1,
    const float* __restrict__ w2T, const float* __restrict__ b2,
    float* __restrict__ outp)
{
    extern __shared__ float smem[];
    float* inS = smem;            // [64][128]
    float* wS  = smem + 8192;     // [64][256]
    float* buf = smem + 24576;    // [256][128]
    const int tid = threadIdx.x;
    const int b = blockIdx.y;
    const int t0 = blockIdx.x << 7;
    const int tl = tid & 31;
    const int wp = tid >> 5;      // 0..31

    // ---- Stage A: skip GEMM, K = 20 layers x 64 channels ----
    ull acc[4][4];
    #pragma unroll
    for (int mp = 0; mp < 4; mp++)
        #pragma unroll
        for (int q = 0; q < 4; q++) acc[mp][q] = 0ULL;

    #pragma unroll 1
    for (int li = 0; li < NL; li++) {
        __syncthreads();
        const float* ab = acts + (size_t)((li * NB + b) * 64) * OUTW_PAD;
        #pragma unroll 1
        for (int i = tid; i < 8192; i += 1024) {
            int dcr = i >> 7, tt = i & 127;
            int t = t0 + tt;
            inS[i] = (t < OUTW) ? ab[(size_t)dcr * OUTW_PAD + t] : 0.f;
        }
        #pragma unroll 1
        for (int i = tid; i < 16384; i += 1024) wS[i] = swT[li * 16384 + i];
        __syncthreads();
        #pragma unroll 1
        for (int kk = 0; kk < 64; kk++) {
            const float* ir = inS + (kk << 7) + tl;
            ull o[4];
            #pragma unroll
            for (int q = 0; q < 4; q++) o[q] = pack2(ir[q << 5]);
            const float* wr = wS + (kk << 8) + (wp << 1);
            #pragma unroll
            for (int mp = 0; mp < 4; mp++) {
                ull w = *(const ull*)(wr + (mp << 6));
                #pragma unroll
                for (int q = 0; q < 4; q++) fma2(acc[mp][q], w, o[q]);
            }
        }
    }
    // total + biasSum, relu -> buf
    #pragma unroll
    for (int mp = 0; mp < 4; mp++) {
        int s0 = (wp << 1) + (mp << 6);
        float sb0 = sbsum[s0], sb1 = sbsum[s0 + 1];
        #pragma unroll
        for (int q = 0; q < 4; q++) {
            float2 v = u2f(acc[mp][q]);
            int tt = tl + (q << 5);
            buf[(s0 << 7) + tt]       = fmaxf(v.x + sb0, 0.f);
            buf[((s0 + 1) << 7) + tt] = fmaxf(v.y + sb1, 0.f);
        }
    }

    // ---- Stage B: pp1 (K=256) ----
    #pragma unroll
    for (int mp = 0; mp < 4; mp++) {
        int s0 = (wp << 1) + (mp << 6);
        ull bv = pack2(b1[s0], b1[s0 + 1]);
        #pragma unroll
        for (int q = 0; q < 4; q++) acc[mp][q] = bv;
    }
    #pragma unroll 1
    for (int kc = 0; kc < 4; kc++) {
        __syncthreads();
        #pragma unroll 1
        for (int i = tid; i < 16384; i += 1024) wS[i] = w1T[(kc << 14) + i];
        __syncthreads();
        #pragma unroll 1
        for (int kk = 0; kk < 64; kk++) {
            const float* ir = buf + (((kc << 6) + kk) << 7) + tl;
            ull o[4];
            #pragma unroll
            for (int q = 0; q < 4; q++) o[q] = pack2(ir[q << 5]);
            const float* wr = wS + (kk << 8) + (wp << 1);
            #pragma unroll
            for (int mp = 0; mp < 4; mp++) {
                ull w = *(const ull*)(wr + (mp << 6));
                #pragma unroll
                for (int q = 0; q < 4; q++) fma2(acc[mp][q], w, o[q]);
            }
        }
    }
    __syncthreads();   // all pp1 reads of buf done
    #pragma unroll
    for (int mp = 0; mp < 4; mp++) {
        int s0 = (wp << 1) + (mp << 6);
        #pragma unroll
        for (int q = 0; q < 4; q++) {
            float2 v = u2f(acc[mp][q]);
            int tt = tl + (q << 5);
            buf[(s0 << 7) + tt]       = fmaxf(v.x, 0.f);
            buf[((s0 + 1) << 7) + tt] = fmaxf(v.y, 0.f);
        }
    }

    // ---- Stage C: pp2 (K=256) -> global out ----
    #pragma unroll
    for (int mp = 0; mp < 4; mp++) {
        int s0 = (wp << 1) + (mp << 6);
        ull bv = pack2(b2[s0], b2[s0 + 1]);
        #pragma unroll
        for (int q = 0; q < 4; q++) acc[mp][q] = bv;
    }
    #pragma unroll 1
    for (int kc = 0; kc < 4; kc++) {
        __syncthreads();
        #pragma unroll 1
        for (int i = tid; i < 16384; i += 1024) wS[i] = w2T[(kc << 14) + i];
        __syncthreads();
        #pragma unroll 1
        for (int kk = 0; kk < 64; kk++) {
            const float* ir = buf + (((kc << 6) + kk) << 7) + tl;
            ull o[4];
            #pragma unroll
            for (int q = 0; q < 4; q++) o[q] = pack2(ir[q << 5]);
            const float* wr = wS + (kk << 8) + (wp << 1);
            #pragma unroll
            for (int mp = 0; mp < 4; mp++) {
                ull w = *(const ull*)(wr + (mp << 6));
                #pragma unroll
                for (int q = 0; q < 4; q++) fma2(acc[mp][q], w, o[q]);
            }
        }
    }
    #pragma unroll
    for (int mp = 0; mp < 4; mp++) {
        int s0 = (wp << 1) + (mp << 6);
        float* op0 = outp + (size_t)((b << 8) + s0) * OUTW + t0;
        float* op1 = op0 + OUTW;
        #pragma unroll
        for (int q = 0; q < 4; q++) {
            int tt = tl + (q << 5);
            if (t0 + tt < OUTW) {
                float2 v = u2f(acc[mp][q]);
                op0[tt] = v.x;
                op1[tt] = v.y;
            }
        }
    }
}

extern "C" void kernel_launch(void* const* d_in, const int* in_sizes, int n_in,
                              void* d_out, int out_size)
{
    const int*   x        = (const int*)d_in[0];
    const float* causal_w = (const float*)d_in[1];
    const float* causal_b = (const float*)d_in[2];
    const float* filt_w   = (const float*)d_in[3];
    const float* filt_b   = (const float*)d_in[4];
    const float* gate_w   = (const float*)d_in[5];
    const float* gate_b   = (const float*)d_in[6];
    const float* dense_w  = (const float*)d_in[7];
    const float* dense_b  = (const float*)d_in[8];
    const float* skip_w   = (const float*)d_in[9];
    const float* skip_b   = (const float*)d_in[10];
    const float* pp1_w    = (const float*)d_in[11];
    const float* pp1_b    = (const float*)d_in[12];
    const float* pp2_w    = (const float*)d_in[13];
    const float* pp2_b    = (const float*)d_in[14];
    float* out = (float*)d_out;

    float *h0, *h1, *acts, *swT, *sbsum, *w1T, *w2T;
    cudaGetSymbolAddress((void**)&h0, g_h0);
    cudaGetSymbolAddress((void**)&h1, g_h1);
    cudaGetSymbolAddress((void**)&acts, g_acts);
    cudaGetSymbolAddress((void**)&swT, g_swT);
    cudaGetSymbolAddress((void**)&sbsum, g_sbsum);
    cudaGetSymbolAddress((void**)&w1T, g_w1T);
    cudaGetSymbolAddress((void**)&w2T, g_w2T);

    static const int dil[NL] = {1, 2, 4, 8, 16, 32, 64, 128, 256, 512,
                                1, 2, 4, 8, 16, 32, 64, 128, 256, 512};

    cudaFuncSetAttribute(layer_kernel,      cudaFuncAttributeMaxDynamicSharedMemorySize, 53376 * 4);
    cudaFuncSetAttribute(causal_kernel,     cudaFuncAttributeMaxDynamicSharedMemorySize, 32768 * 4);
    cudaFuncSetAttribute(fused_post_kernel, cudaFuncAttributeMaxDynamicSharedMemorySize, 57344 * 4);

    // prep (independent of layer chain)
    transpose_kernel<<<256, 256>>>(pp1_w, w1T);
    transpose_kernel<<<256, 256>>>(pp2_w, w2T);
    skipw_kernel<<<NL * ND, 256>>>(skip_w, swT);
    sbsum_kernel<<<1, 256>>>(skip_b, sbsum);

    dim3 cg((NT - 1 + 255) / 256, NB);
    causal_kernel<<<cg, 256, 32768 * 4>>>(x, causal_w, causal_b, h0);

    float* hc = h0;
    float* hn = h1;
    int Lh = NT - 1;
    for (int i = 0; i < NL; i++) {
        int d = dil[i];
        int Ti = Lh - d;
        int off = Ti - OUTW;
        dim3 g((Ti + TT - 1) / TT, NB);
        layer_kernel<<<g, 1024, 53376 * 4>>>(
            hc, hn,
            filt_w + (size_t)i * ND * NR * 2, filt_b + (size_t)i * ND,
            gate_w + (size_t)i * ND * NR * 2, gate_b + (size_t)i * ND,
            dense_w + (size_t)i * NR * ND,    dense_b + (size_t)i * NR,
            acts, i, d, Lh, Ti, off);
        float* tmp = hc; hc = hn; hn = tmp;
        Lh = Ti;
    }

    dim3 pg((OUTW + 127) / 128, NB);
    fused_post_kernel<<<pg, 1024, 57344 * 4>>>(acts, swT, sbsum,
                                               w1T, pp1_b, w2T, pp2_b, out);
}

// round 9
// speedup vs baseline: 1.6769x; 1.0727x over previous
#include <cuda_runtime.h>
#include <math.h>

#define NB 8
#define NT 16384
#define NQ 256
#define NR 64
#define ND 64
#define NS 256
#define NL 20
#define OUTW 14337
#define OUTW_PAD 14368
#define TT 256
#define AS 260   // act row stride (16B-aligned rows, conflict-free)
#define DS 68    // dwT row stride (16B-aligned rows)

typedef unsigned long long ull;

__device__ __forceinline__ ull pack2(float x) {
    ull r; asm("mov.b64 %0, {%1, %1};" : "=l"(r) : "f"(x)); return r;
}
__device__ __forceinline__ ull pack2(float lo, float hi) {
    ull r; asm("mov.b64 %0, {%1, %2};" : "=l"(r) : "f"(lo), "f"(hi)); return r;
}
__device__ __forceinline__ void fma2(ull& d, ull a, ull b) {
    asm("fma.rn.f32x2 %0, %1, %2, %0;" : "+l"(d) : "l"(a), "l"(b));
}
__device__ __forceinline__ float2 u2f(ull v) {
    float2 f; asm("mov.b64 {%0, %1}, %2;" : "=f"(f.x), "=f"(f.y) : "l"(v)); return f;
}

// Scratch (device globals; no allocation allowed)
__device__ float g_h0[NB * NR * NT];
__device__ float g_h1[NB * NR * NT];
__device__ float g_acts[NL * NB * NR * OUTW_PAD];   // gated activations per layer (skip inputs)
__device__ float g_swT[NL * ND * NS];               // [k=li*64+dc][s]
__device__ float g_sbsum[NS];
__device__ float g_w1T[NS * NS];
__device__ float g_w2T[NQ * NS];

// wT[k][s] = w[s][k], 256x256
__global__ void transpose_kernel(const float* __restrict__ w, float* __restrict__ wT) {
    int i = blockIdx.x * 256 + threadIdx.x;
    int k = i >> 8, s = i & 255;
    wT[i] = w[(s << 8) + k];
}

// swT[k][s] = skip_w[li][s][dc], k = li*64+dc
__global__ void skipw_kernel(const float* __restrict__ sw, float* __restrict__ swT) {
    int k = blockIdx.x;          // 0..1279
    int s = threadIdx.x;         // 0..255
    int li = k >> 6, dc = k & 63;
    swT[k * NS + s] = sw[li * (NS * ND) + s * ND + dc];
}

// sbsum[s] = sum_li skip_b[li][s]
__global__ void sbsum_kernel(const float* __restrict__ sb, float* __restrict__ sbsum) {
    int s = threadIdx.x;
    float v = 0.f;
    #pragma unroll
    for (int li = 0; li < NL; li++) v += sb[li * NS + s];
    sbsum[s] = v;
}

// h[b][r][t] = cw[r][x[b,t]][0] + cw[r][x[b,t+1]][1] + cb[r]   (one-hot conv == gather)
__global__ void __launch_bounds__(256) causal_kernel(
    const int* __restrict__ x, const float* __restrict__ cw,
    const float* __restrict__ cb, float* __restrict__ h)
{
    extern __shared__ float sm[];               // 32768 floats: cw [r][q][k]
    __shared__ float cbS[64];
    for (int i = threadIdx.x; i < NR * NQ * 2; i += 256) sm[i] = cw[i];
    if (threadIdx.x < 64) cbS[threadIdx.x] = cb[threadIdx.x];
    __syncthreads();
    int b = blockIdx.y;
    int t = blockIdx.x * 256 + threadIdx.x;
    if (t >= NT - 1) return;
    int q0 = x[b * NT + t] * 2;
    int q1 = x[b * NT + t + 1] * 2 + 1;
    float* hp = h + ((size_t)b << 20) + t;
    #pragma unroll 4
    for (int r = 0; r < 64; r++) {
        hp[r << 14] = sm[(r << 9) + q0] + sm[(r << 9) + q1] + cbS[r];
    }
}

// Fused WaveNet layer (no skip), 1024 threads, 256 time cols per CTA.
// Phase 1: thread tile = 4 channels x 4 time cols (channel-packed weights).
// Phase 2: thread tile = 4 r x 4 time cols (time-packed, dwT transposed).
// SMEM layout (floats):
//   [0, 8192)        wfT (k,r,dc)       -- dead after phase1
//   [8192, 16384)    wgT (k,r,dc)       -- dead after phase1
//   [0, 16640)       act [64][260]      -- written after phase1 (overlaps wfT/wgT)
//   [16640, 20992)   dwT [dcc][68]      -- transposed dense weights
//   [20992, 37376)   hA  [64][256]      -- dead after phase1
//   [37376, 53760)   hB  [64][256]
// total 53760 floats = 215040 B
__global__ void __launch_bounds__(1024) layer_kernel(
    const float* __restrict__ hcur, float* __restrict__ hnext,
    const float* __restrict__ fw, const float* __restrict__ fb,
    const float* __restrict__ gw, const float* __restrict__ gb,
    const float* __restrict__ dw, const float* __restrict__ db,
    float* __restrict__ acts,
    int li, int dil, int Lh, int Ti, int off)
{
    extern __shared__ float smem[];
    float* wfT = smem;
    float* wgT = smem + 8192;
    float* act = smem;              // [64][260], valid after phase1
    float* dwT = smem + 16640;
    float* hA  = smem + 20992;
    float* hB  = smem + 37376;

    const int tid = threadIdx.x;
    const int b = blockIdx.y;
    const int t0 = blockIdx.x * TT;

    // stage weights; fw/gw transposed to (k,r,dc); dw transposed to (dcc,r)
    #pragma unroll 1
    for (int i = tid; i < 8192; i += 1024) {
        int dcq = i >> 7, r = (i >> 1) & 63, k = i & 1;
        int si = (k << 12) + (r << 6) + dcq;
        wfT[si] = fw[i];
        wgT[si] = gw[i];
    }
    #pragma unroll 1
    for (int i = tid; i < 4096; i += 1024) {
        int r = i >> 6, dcc = i & 63;
        dwT[dcc * DS + r] = dw[i];
    }

    const float* hbase = hcur + ((size_t)b << 20);
    #pragma unroll 1
    for (int i = tid << 1; i < 64 * TT; i += 2048) {
        int r = i >> 8, tt = i & 255;
        int ta = t0 + tt;
        float2 va, vb;
        if (ta + 1 < Lh) {
            va = *(const float2*)(hbase + (r << 14) + ta);
        } else {
            va.x = (ta < Lh) ? hbase[(r << 14) + ta] : 0.f;
            va.y = 0.f;
        }
        int tb = ta + dil;
        vb.x = (tb < Lh) ? hbase[(r << 14) + tb] : 0.f;
        vb.y = (tb + 1 < Lh) ? hbase[(r << 14) + tb + 1] : 0.f;
        *(float2*)(hA + i) = va;
        *(float2*)(hB + i) = vb;
    }
    __syncthreads();

    // ---- Phase 1: filter/gate GEMM (K=64, 2 taps) ----
    // cg = col group (4 cols), dg = channel group (4 channels)
    const int cg = tid & 63;
    const int dg = tid >> 6;         // 0..15
    const int dc0 = dg << 2;
    ull facc[2][4], gacc[2][4];      // [channel pair][col], channel-packed
    {
        ull fbp0 = pack2(fb[dc0], fb[dc0 + 1]);
        ull fbp1 = pack2(fb[dc0 + 2], fb[dc0 + 3]);
        ull gbp0 = pack2(gb[dc0], gb[dc0 + 1]);
        ull gbp1 = pack2(gb[dc0 + 2], gb[dc0 + 3]);
        #pragma unroll
        for (int c = 0; c < 4; c++) {
            facc[0][c] = fbp0; facc[1][c] = fbp1;
            gacc[0][c] = gbp0; gacc[1][c] = gbp1;
        }
        const float* hap = hA + (cg << 2);
        const float* hbp = hB + (cg << 2);
        #pragma unroll 2
        for (int r = 0; r < 64; r++) {
            float4 A = *(const float4*)(hap + (r << 8));
            float4 C = *(const float4*)(hbp + (r << 8));
            ull a[4], c2[4];
            a[0] = pack2(A.x); a[1] = pack2(A.y); a[2] = pack2(A.z); a[3] = pack2(A.w);
            c2[0] = pack2(C.x); c2[1] = pack2(C.y); c2[2] = pack2(C.z); c2[3] = pack2(C.w);
            // filter weights (broadcast LDS.128: channel pairs)
            {
                ulonglong2 W0 = *(const ulonglong2*)(wfT + (r << 6) + dc0);
                ulonglong2 W1 = *(const ulonglong2*)(wfT + 4096 + (r << 6) + dc0);
                #pragma unroll
                for (int c = 0; c < 4; c++) {
                    fma2(facc[0][c], W0.x, a[c]);
                    fma2(facc[1][c], W0.y, a[c]);
                    fma2(facc[0][c], W1.x, c2[c]);
                    fma2(facc[1][c], W1.y, c2[c]);
                }
            }
            // gate weights
            {
                ulonglong2 W0 = *(const ulonglong2*)(wgT + (r << 6) + dc0);
                ulonglong2 W1 = *(const ulonglong2*)(wgT + 4096 + (r << 6) + dc0);
                #pragma unroll
                for (int c = 0; c < 4; c++) {
                    fma2(gacc[0][c], W0.x, a[c]);
                    fma2(gacc[1][c], W0.y, a[c]);
                    fma2(gacc[0][c], W1.x, c2[c]);
                    fma2(gacc[1][c], W1.y, c2[c]);
                }
            }
        }
        // out = tanh(f) * sigmoid(g)  (lanes are channels here)
        #pragma unroll
        for (int p = 0; p < 2; p++) {
            #pragma unroll
            for (int c = 0; c < 4; c++) {
                float2 f = u2f(facc[p][c]);
                float2 g = u2f(gacc[p][c]);
                float ef0 = __expf(fminf(-2.f * f.x, 80.f));
                float ef1 = __expf(fminf(-2.f * f.y, 80.f));
                float eg0 = __expf(fminf(-g.x, 80.f));
                float eg1 = __expf(fminf(-g.y, 80.f));
                float o0 = __fdividef(1.f - ef0, (1.f + ef0) * (1.f + eg0));
                float o1 = __fdividef(1.f - ef1, (1.f + ef1) * (1.f + eg1));
                facc[p][c] = pack2(o0, o1);
            }
        }
    }
    __syncthreads();    // all wfT/wgT/hA reads done

    // write activation tile: rows dc0..dc0+3, cols 4cg..4cg+3 (STS.128, conflict-free)
    {
        float2 v0 = u2f(facc[0][0]), v1 = u2f(facc[0][1]),
               v2 = u2f(facc[0][2]), v3 = u2f(facc[0][3]);
        float2 w0 = u2f(facc[1][0]), w1 = u2f(facc[1][1]),
               w2 = u2f(facc[1][2]), w3 = u2f(facc[1][3]);
        float* rbase = act + dc0 * AS + (cg << 2);
        *(float4*)(rbase)          = make_float4(v0.x, v1.x, v2.x, v3.x);
        *(float4*)(rbase + AS)     = make_float4(v0.y, v1.y, v2.y, v3.y);
        *(float4*)(rbase + 2 * AS) = make_float4(w0.x, w1.x, w2.x, w3.x);
        *(float4*)(rbase + 3 * AS) = make_float4(w0.y, w1.y, w2.y, w3.y);
    }
    __syncthreads();

    // store act tile to global (skip input), cols >= off, aligned to skip index
    {
        float* abase = acts + (size_t)((li * NB + b) * 64) * OUTW_PAD - off;
        #pragma unroll 1
        for (int i = tid; i < 64 * TT; i += 1024) {
            int dcw = i >> 8, tt = i & 255;
            int tgl = t0 + tt;
            if (tgl >= off && tgl < Ti)
                abase[(size_t)dcw * OUTW_PAD + tgl] = act[dcw * AS + tt];
        }
    }

    const int tl = tid & 31;
    const int wp = tid >> 5;   // 0..31

    // ---- Phase 2: dense 1x1 (D->R) + residual -> hnext, 4r x 4cols ----
    {
        const int rg = wp >> 1;            // 0..15
        const int half = wp & 1;
        const int r0 = rg << 2;
        const int c0 = (half << 7) + (tl << 2);
        ull acc[4][2];
        #pragma unroll
        for (int m = 0; m < 4; m++) {
            ull dbv = pack2(db[r0 + m]);
            acc[m][0] = dbv; acc[m][1] = dbv;
        }
        #pragma unroll 1
        for (int dcc = 0; dcc < 64; dcc++) {
            ulonglong2 o = *(const ulonglong2*)(act + dcc * AS + c0);
            float4 w4 = *(const float4*)(dwT + dcc * DS + r0);   // broadcast
            ull w0 = pack2(w4.x), w1 = pack2(w4.y), w2 = pack2(w4.z), w3 = pack2(w4.w);
            fma2(acc[0][0], w0, o.x); fma2(acc[0][1], w0, o.y);
            fma2(acc[1][0], w1, o.x); fma2(acc[1][1], w1, o.y);
            fma2(acc[2][0], w2, o.x); fma2(acc[2][1], w2, o.y);
            fma2(acc[3][0], w3, o.x); fma2(acc[3][1], w3, o.y);
        }
        float* hnb = hnext + ((size_t)b << 20);
        const int tgl = t0 + c0;
        #pragma unroll
        for (int m = 0; m < 4; m++) {
            int r = r0 + m;
            float4 hv = *(const float4*)(hB + (r << 8) + c0);
            float2 v0 = u2f(acc[m][0]);
            float2 v1 = u2f(acc[m][1]);
            float4 v = make_float4(v0.x + hv.x, v0.y + hv.y, v1.x + hv.z, v1.y + hv.w);
            if (tgl + 3 < Ti) {
                *(float4*)(hnb + (r << 14) + tgl) = v;
            } else {
                if (tgl < Ti)     hnb[(r << 14) + tgl]     = v.x;
                if (tgl + 1 < Ti) hnb[(r << 14) + tgl + 1] = v.y;
                if (tgl + 2 < Ti) hnb[(r << 14) + tgl + 2] = v.z;
            }
        }
    }
}

// Fused post chain: total(K=1280 GEMM over acts) -> +sbsum,relu -> pp1(K=256)
//   -> +b1,relu -> pp2(K=256) -> +b2 -> out.   1024 threads, 128 time cols/CTA.
// smem: inS [64][128]=8192, wS [64][256]=16384, buf [256][128]=32768 -> 57344 floats
__global__ void __launch_bounds__(1024) fused_post_kernel(
    const float* __restrict__ acts, const float* __restrict__ swT,
    const float* __restrict__ sbsum,
    const float* __restrict__ w1T, const float* __restrict__ b1,
    const float* __restrict__ w2T, const float* __restrict__ b2,
    float* __restrict__ outp)
{
    extern __shared__ float smem[];
    float* inS = smem;            // [64][128]
    float* wS  = smem + 8192;     // [64][256]
    float* buf = smem + 24576;    // [256][128]
    const int tid = threadIdx.x;
    const int b = blockIdx.y;
    const int t0 = blockIdx.x << 7;
    const int tl = tid & 31;
    const int wp = tid >> 5;      // 0..31

    // ---- Stage A: skip GEMM, K = 20 layers x 64 channels ----
    ull acc[4][4];
    #pragma unroll
    for (int mp = 0; mp < 4; mp++)
        #pragma unroll
        for (int q = 0; q < 4; q++) acc[mp][q] = 0ULL;

    #pragma unroll 1
    for (int li = 0; li < NL; li++) {
        __syncthreads();
        const float* ab = acts + (size_t)((li * NB + b) * 64) * OUTW_PAD;
        #pragma unroll 1
        for (int i = tid; i < 8192; i += 1024) {
            int dcr = i >> 7, tt = i & 127;
            int t = t0 + tt;
            inS[i] = (t < OUTW) ? ab[(size_t)dcr * OUTW_PAD + t] : 0.f;
        }
        #pragma unroll 1
        for (int i = tid; i < 16384; i += 1024) wS[i] = swT[li * 16384 + i];
        __syncthreads();
        #pragma unroll 1
        for (int kk = 0; kk < 64; kk++) {
            const float* ir = inS + (kk << 7) + tl;
            ull o[4];
            #pragma unroll
            for (int q = 0; q < 4; q++) o[q] = pack2(ir[q << 5]);
            const float* wr = wS + (kk << 8) + (wp << 1);
            #pragma unroll
            for (int mp = 0; mp < 4; mp++) {
                ull w = *(const ull*)(wr + (mp << 6));
                #pragma unroll
                for (int q = 0; q < 4; q++) fma2(acc[mp][q], w, o[q]);
            }
        }
    }
    // total + biasSum, relu -> buf
    #pragma unroll
    for (int mp = 0; mp < 4; mp++) {
        int s0 = (wp << 1) + (mp << 6);
        float sb0 = sbsum[s0], sb1 = sbsum[s0 + 1];
        #pragma unroll
        for (int q = 0; q < 4; q++) {
            float2 v = u2f(acc[mp][q]);
            int tt = tl + (q << 5);
            buf[(s0 << 7) + tt]       = fmaxf(v.x + sb0, 0.f);
            buf[((s0 + 1) << 7) + tt] = fmaxf(v.y + sb1, 0.f);
        }
    }

    // ---- Stage B: pp1 (K=256) ----
    #pragma unroll
    for (int mp = 0; mp < 4; mp++) {
        int s0 = (wp << 1) + (mp << 6);
        ull bv = pack2(b1[s0], b1[s0 + 1]);
        #pragma unroll
        for (int q = 0; q < 4; q++) acc[mp][q] = bv;
    }
    #pragma unroll 1
    for (int kc = 0; kc < 4; kc++) {
        __syncthreads();
        #pragma unroll 1
        for (int i = tid; i < 16384; i += 1024) wS[i] = w1T[(kc << 14) + i];
        __syncthreads();
        #pragma unroll 1
        for (int kk = 0; kk < 64; kk++) {
            const float* ir = buf + (((kc << 6) + kk) << 7) + tl;
            ull o[4];
            #pragma unroll
            for (int q = 0; q < 4; q++) o[q] = pack2(ir[q << 5]);
            const float* wr = wS + (kk << 8) + (wp << 1);
            #pragma unroll
            for (int mp = 0; mp < 4; mp++) {
                ull w = *(const ull*)(wr + (mp << 6));
                #pragma unroll
                for (int q = 0; q < 4; q++) fma2(acc[mp][q], w, o[q]);
            }
        }
    }
    __syncthreads();   // all pp1 reads of buf done
    #pragma unroll
    for (int mp = 0; mp < 4; mp++) {
        int s0 = (wp << 1) + (mp << 6);
        #pragma unroll
        for (int q = 0; q < 4; q++) {
            float2 v = u2f(acc[mp][q]);
            int tt = tl + (q << 5);
            buf[(s0 << 7) + tt]       = fmaxf(v.x, 0.f);
            buf[((s0 + 1) << 7) + tt] = fmaxf(v.y, 0.f);
        }
    }

    // ---- Stage C: pp2 (K=256) -> global out ----
    #pragma unroll
    for (int mp = 0; mp < 4; mp++) {
        int s0 = (wp << 1) + (mp << 6);
        ull bv = pack2(b2[s0], b2[s0 + 1]);
        #pragma unroll
        for (int q = 0; q < 4; q++) acc[mp][q] = bv;
    }
    #pragma unroll 1
    for (int kc = 0; kc < 4; kc++) {
        __syncthreads();
        #pragma unroll 1
        for (int i = tid; i < 16384; i += 1024) wS[i] = w2T[(kc << 14) + i];
        __syncthreads();
        #pragma unroll 1
        for (int kk = 0; kk < 64; kk++) {
            const float* ir = buf + (((kc << 6) + kk) << 7) + tl;
            ull o[4];
            #pragma unroll
            for (int q = 0; q < 4; q++) o[q] = pack2(ir[q << 5]);
            const float* wr = wS + (kk << 8) + (wp << 1);
            #pragma unroll
            for (int mp = 0; mp < 4; mp++) {
                ull w = *(const ull*)(wr + (mp << 6));
                #pragma unroll
                for (int q = 0; q < 4; q++) fma2(acc[mp][q], w, o[q]);
            }
        }
    }
    #pragma unroll
    for (int mp = 0; mp < 4; mp++) {
        int s0 = (wp << 1) + (mp << 6);
        float* op0 = outp + (size_t)((b << 8) + s0) * OUTW + t0;
        float* op1 = op0 + OUTW;
        #pragma unroll
        for (int q = 0; q < 4; q++) {
            int tt = tl + (q << 5);
            if (t0 + tt < OUTW) {
                float2 v = u2f(acc[mp][q]);
                op0[tt] = v.x;
                op1[tt] = v.y;
            }
        }
    }
}

extern "C" void kernel_launch(void* const* d_in, const int* in_sizes, int n_in,
                              void* d_out, int out_size)
{
    const int*   x        = (const int*)d_in[0];
    const float* causal_w = (const float*)d_in[1];
    const float* causal_b = (const float*)d_in[2];
    const float* filt_w   = (const float*)d_in[3];
    const float* filt_b   = (const float*)d_in[4];
    const float* gate_w   = (const float*)d_in[5];
    const float* gate_b   = (const float*)d_in[6];
    const float* dense_w  = (const float*)d_in[7];
    const float* dense_b  = (const float*)d_in[8];
    const float* skip_w   = (const float*)d_in[9];
    const float* skip_b   = (const float*)d_in[10];
    const float* pp1_w    = (const float*)d_in[11];
    const float* pp1_b    = (const float*)d_in[12];
    const float* pp2_w    = (const float*)d_in[13];
    const float* pp2_b    = (const float*)d_in[14];
    float* out = (float*)d_out;

    float *h0, *h1, *acts, *swT, *sbsum, *w1T, *w2T;
    cudaGetSymbolAddress((void**)&h0, g_h0);
    cudaGetSymbolAddress((void**)&h1, g_h1);
    cudaGetSymbolAddress((void**)&acts, g_acts);
    cudaGetSymbolAddress((void**)&swT, g_swT);
    cudaGetSymbolAddress((void**)&sbsum, g_sbsum);
    cudaGetSymbolAddress((void**)&w1T, g_w1T);
    cudaGetSymbolAddress((void**)&w2T, g_w2T);

    static const int dil[NL] = {1, 2, 4, 8, 16, 32, 64, 128, 256, 512,
                                1, 2, 4, 8, 16, 32, 64, 128, 256, 512};

    cudaFuncSetAttribute(layer_kernel,      cudaFuncAttributeMaxDynamicSharedMemorySize, 53760 * 4);
    cudaFuncSetAttribute(causal_kernel,     cudaFuncAttributeMaxDynamicSharedMemorySize, 32768 * 4);
    cudaFuncSetAttribute(fused_post_kernel, cudaFuncAttributeMaxDynamicSharedMemorySize, 57344 * 4);

    // prep (independent of layer chain)
    transpose_kernel<<<256, 256>>>(pp1_w, w1T);
    transpose_kernel<<<256, 256>>>(pp2_w, w2T);
    skipw_kernel<<<NL * ND, 256>>>(skip_w, swT);
    sbsum_kernel<<<1, 256>>>(skip_b, sbsum);

    dim3 cg((NT - 1 + 255) / 256, NB);
    causal_kernel<<<cg, 256, 32768 * 4>>>(x, causal_w, causal_b, h0);

    float* hc = h0;
    float* hn = h1;
    int Lh = NT - 1;
    for (int i = 0; i < NL; i++) {
        int d = dil[i];
        int Ti = Lh - d;
        int off = Ti - OUTW;
        dim3 g((Ti + TT - 1) / TT, NB);
        layer_kernel<<<g, 1024, 53760 * 4>>>(
            hc, hn,
            filt_w + (size_t)i * ND * NR * 2, filt_b + (size_t)i * ND,
            gate_w + (size_t)i * ND * NR * 2, gate_b + (size_t)i * ND,
            dense_w + (size_t)i * NR * ND,    dense_b + (size_t)i * NR,
            acts, i, d, Lh, Ti, off);
        float* tmp = hc; hc = hn; hn = tmp;
        Lh = Ti;
    }

    dim3 pg((OUTW + 127) / 128, NB);
    fused_post_kernel<<<pg, 1024, 57344 * 4>>>(acts, swT, sbsum,
                                               w1T, pp1_b, w2T, pp2_b, out);
}